// round 15
// baseline (speedup 1.0000x reference)
#include <cuda_runtime.h>

// Problem constants
#define NB 2
#define LB 1024
#define EB 256
#define HB 8
#define PB 4
#define KK 4
#define DB 32
#define MROWS (NB*LB)        // 2048
#define NH (NB*HB)           // 16
#define QPB (LB*PB)          // 4096 queries per batch-head
#define QTOT (NH*QPB)        // 65536
#define TS 16                // refs per tile
#define FULLM 0xffffffffu

// ---------------- scratch (device globals) ---------------------------------
__device__ float  g_val [MROWS*EB];
__device__ float  g_off [MROWS*96];
__device__ float  g_attn[MROWS*32];
__device__ float  g_attw[QTOT];
__device__ float4 g_sl  [QTOT];             // sampling loc (x,y,z,|s|^2)
__device__ int    g_qperm[QTOT];            // per-b permutation (Morton sorted)
__device__ float4 g_refPts[NB][LB];         // Morton-sorted refs (x,y,z,|r|^2)
__device__ int    g_refIdx[NB][LB];         // original ref index
__device__ int    g_cellTile[NB][512];      // Morton cell -> covering tile
__device__ float4 g_pd[QTOT*2];             // partial top-4 dists (half A, B)
__device__ int4   g_pi[QTOT*2];             // partial top-4 positions
__device__ int    g_idx [QTOT*KK];
__device__ float  g_w   [QTOT*KK];
__device__ float  g_A   [MROWS*EB];

// ---------------- packed f32x2 helpers (Blackwell) --------------------------
typedef unsigned long long u64;
__device__ __forceinline__ u64 pk(float lo, float hi) {
    u64 v; asm("mov.b64 %0, {%1, %2};" : "=l"(v) : "f"(lo), "f"(hi)); return v;
}
__device__ __forceinline__ void upk(u64 v, float& lo, float& hi) {
    asm("mov.b64 {%0, %1}, %2;" : "=f"(lo), "=f"(hi) : "l"(v));
}
__device__ __forceinline__ u64 fma2(u64 a, u64 b, u64 c) {
    u64 d; asm("fma.rn.f32x2 %0, %1, %2, %3;" : "=l"(d) : "l"(a), "l"(b), "l"(c)); return d;
}
__device__ __forceinline__ u64 mul2(u64 a, u64 b) {
    u64 d; asm("mul.rn.f32x2 %0, %1, %2;" : "=l"(d) : "l"(a), "l"(b)); return d;
}
__device__ __forceinline__ u64 add2(u64 a, u64 b) {
    u64 d; asm("add.rn.f32x2 %0, %1, %2;" : "=l"(d) : "l"(a), "l"(b)); return d;
}

// ---------------- Morton helpers -------------------------------------------
__device__ __forceinline__ int spread3(int x) {
    return (x & 1) | ((x & 2) << 2) | ((x & 4) << 4);
}
__device__ __forceinline__ int cell8(float v) {
    int c = (int)floorf(v * 8.f);
    return min(max(c, 0), 7);
}
__device__ __forceinline__ int morton(float x, float y, float z) {
    return spread3(cell8(x)) | (spread3(cell8(y)) << 1) | (spread3(cell8(z)) << 2);
}

// ============================================================================
// Kernel 1: fused off/attn GEMM 32-row tiles (blocks 0..127) + refsort (128,129)
// ============================================================================

__device__ void refsort_body(char* sm, const float* __restrict__ rp, int n) {
    float* sx        = (float*)(sm);
    float* sy        = (float*)(sm + 4096);
    float* sz        = (float*)(sm + 8192);
    int*   sidx      = (int*)  (sm + 12288);
    int*   skey      = (int*)  (sm + 16384);
    int*   sortedKey = (int*)  (sm + 20480);
    int*   cnt       = (int*)  (sm + 24576);
    int*   bstart    = (int*)  (sm + 26624);
    int*   sCT       = (int*)  (sm + 28672);
    int*   wsum      = (int*)  (sm + 30720);
    const int tid = threadIdx.x;
    const int lane = tid & 31, w = tid >> 5;
    const float* rpb = rp + n*LB*3;

    cnt[tid] = 0; cnt[tid + 256] = 0;
    __syncthreads();
    #pragma unroll
    for (int j = 0; j < 4; j++) {
        int i = tid + j*256;
        float x = rpb[3*i], y = rpb[3*i+1], z = rpb[3*i+2];
        int key = morton(x, y, z);
        skey[i] = key;
        atomicAdd(&cnt[key], 1);
    }
    __syncthreads();
    int c0 = cnt[2*tid], c1 = cnt[2*tid + 1];
    int s = c0 + c1, v = s;
    #pragma unroll
    for (int off = 1; off < 32; off <<= 1) {
        int u = __shfl_up_sync(FULLM, v, off);
        if (lane >= off) v += u;
    }
    if (lane == 31) wsum[w] = v;
    __syncthreads();
    if (tid == 0) {
        int acc = 0;
        #pragma unroll
        for (int i = 0; i < 8; i++) { int t = wsum[i]; wsum[i] = acc; acc += t; }
    }
    __syncthreads();
    int excl = v - s + wsum[w];
    bstart[2*tid] = excl; bstart[2*tid + 1] = excl + c0;
    __syncthreads();
    #pragma unroll
    for (int j = 0; j < 4; j++) {
        int i = tid + j*256;
        int slot = atomicAdd(&bstart[skey[i]], 1);
        sx[slot] = rpb[3*i]; sy[slot] = rpb[3*i+1]; sz[slot] = rpb[3*i+2];
        sidx[slot] = i;
        sortedKey[slot] = skey[i];
    }
    __syncthreads();
    #pragma unroll
    for (int j = 0; j < 4; j++) {
        int i = tid + j*256;
        float x = sx[i], y = sy[i], z = sz[i];
        g_refPts[n][i] = make_float4(x, y, z, x*x + y*y + z*z);
        g_refIdx[n][i] = sidx[i];
    }

    sCT[tid] = -1; sCT[tid + 256] = -1;
    __syncthreads();
    #pragma unroll
    for (int j = 0; j < 4; j++) {
        int slot = tid + j*256;
        int k = sortedKey[slot];
        if (slot == 0 || sortedKey[slot-1] != k) sCT[k] = slot >> 4;
    }
    __syncthreads();
    for (int off = 1; off < 512; off <<= 1) {
        int a0 = sCT[tid],       a1 = sCT[tid + 256];
        int b0 = (tid >= off)       ? sCT[tid - off]       : -1;
        int b1 = (tid + 256 >= off) ? sCT[tid + 256 - off] : -1;
        __syncthreads();
        sCT[tid]       = (a0 != -1) ? a0 : b0;
        sCT[tid + 256] = (a1 != -1) ? a1 : b1;
        __syncthreads();
    }
    g_cellTile[n][tid]       = (sCT[tid] == -1) ? 0 : sCT[tid];
    g_cellTile[n][tid + 256] = (sCT[tid + 256] == -1) ? 0 : sCT[tid + 256];
}

// ---- 32-row x 64-col double-buffered gemm helpers --------------------------
#define AS32(buf,k,m) AsP[(buf)*512  + (k)*32 + (m)]
#define BS32(buf,k,n) BsP[(buf)*1088 + (k)*68 + (n)]

__device__ void oa_gemm_body(char* sm, const float* __restrict__ A,
                             const float* __restrict__ Wo, const float* __restrict__ bo,
                             const float* __restrict__ Wa, const float* __restrict__ ba,
                             int blk) {
    float* AsP = (float*)sm;
    float* BsP = (float*)(sm + 4096);
    const int tid = threadIdx.x;
    const int tx = tid & 15, ty = tid >> 4;
    const int colBase = (blk & 1) * 64;
    const int rowBase = (blk >> 1) * 32;
    float acc[2][4];
    #pragma unroll
    for (int i = 0; i < 2; i++)
        #pragma unroll
        for (int j = 0; j < 4; j++) acc[i][j] = 0.f;

    #pragma unroll
    for (int i = 0; i < 2; i++) {
        int idx = tid + i*256;
        int m = idx >> 4, k = idx & 15;
        AS32(0, k, m) = A[(rowBase + m)*256 + k];
    }
    #pragma unroll
    for (int i = 0; i < 4; i++) {
        int idx = tid + i*256;
        int k2 = idx >> 6, nn = idx & 63;
        int gn = colBase + nn;
        BS32(0, k2, nn) = (gn < 96) ? Wo[k2*96 + gn] : Wa[k2*32 + (gn - 96)];
    }
    __syncthreads();

    #pragma unroll 4
    for (int k0 = 0; k0 < 256; k0 += 16) {
        const int cur = (k0 >> 4) & 1, nxt = cur ^ 1;
        float ra[2], rb[4];
        const bool more = (k0 + 16) < 256;
        if (more) {
            #pragma unroll
            for (int i = 0; i < 2; i++) {
                int idx = tid + i*256;
                int m = idx >> 4, k = idx & 15;
                ra[i] = A[(rowBase + m)*256 + k0 + 16 + k];
            }
            #pragma unroll
            for (int i = 0; i < 4; i++) {
                int idx = tid + i*256;
                int k2 = idx >> 6, nn = idx & 63;
                int gn = colBase + nn;
                int gk = k0 + 16 + k2;
                rb[i] = (gn < 96) ? Wo[gk*96 + gn] : Wa[gk*32 + (gn - 96)];
            }
        }
        #pragma unroll
        for (int kk = 0; kk < 16; kk++) {
            float2 av = *(const float2*)&AS32(cur, kk, ty*2);
            float4 bv = *(const float4*)&BS32(cur, kk, tx*4);
            float a[2] = {av.x, av.y};
            float b[4] = {bv.x, bv.y, bv.z, bv.w};
            #pragma unroll
            for (int i = 0; i < 2; i++)
                #pragma unroll
                for (int j = 0; j < 4; j++)
                    acc[i][j] = fmaf(a[i], b[j], acc[i][j]);
        }
        if (more) {
            #pragma unroll
            for (int i = 0; i < 2; i++) {
                int idx = tid + i*256;
                int m = idx >> 4, k = idx & 15;
                AS32(nxt, k, m) = ra[i];
            }
            #pragma unroll
            for (int i = 0; i < 4; i++) {
                int idx = tid + i*256;
                int k2 = idx >> 6, nn = idx & 63;
                BS32(nxt, k2, nn) = rb[i];
            }
            __syncthreads();
        }
    }

    #pragma unroll
    for (int i = 0; i < 2; i++) {
        int gm = rowBase + ty*2 + i;
        #pragma unroll
        for (int j = 0; j < 4; j++) {
            int gn = colBase + tx*4 + j;
            float v = acc[i][j];
            if (gn < 96) g_off[gm*96 + gn]         = v + bo[gn];
            else         g_attn[gm*32 + (gn - 96)] = v + ba[gn - 96];
        }
    }
}

__global__ void oa_refsort_k(const float* __restrict__ A,
                             const float* __restrict__ Wo, const float* __restrict__ bo,
                             const float* __restrict__ Wa, const float* __restrict__ ba,
                             const float* __restrict__ rp) {
    __shared__ __align__(16) char sm[30752];
    if (blockIdx.x < 128) oa_gemm_body(sm, A, Wo, bo, Wa, ba, blockIdx.x);
    else                  refsort_body(sm, rp, blockIdx.x - 128);
}

// ============================================================================
// Kernel 2: fused prep + Morton counting sort (16 blocks, 1024 thr)
// ============================================================================
__global__ void sortprep_k(const float* __restrict__ rp) {
    __shared__ int skey[QPB];
    __shared__ int cnt[512];
    __shared__ int bstart[512];
    __shared__ int wsum[16];
    const int b = blockIdx.x, tid = threadIdx.x;
    const int lane = tid & 31, w = tid >> 5;
    const int n = b >> 3, h = b & 7;

    if (tid < 512) cnt[tid] = 0;
    __syncthreads();

    #pragma unroll
    for (int j = 0; j < 4; j++) {
        int qi = tid + j*1024;
        int l = qi >> 2, p = qi & 3;
        int m = n*LB + l;
        int q = b*QPB + qi;

        float x = g_attn[m*32 + h*4 + p];
        float mx = x;
        mx = fmaxf(mx, __shfl_xor_sync(FULLM, mx, 1));
        mx = fmaxf(mx, __shfl_xor_sync(FULLM, mx, 2));
        float e = expf(x - mx);
        float se = e;
        se += __shfl_xor_sync(FULLM, se, 1);
        se += __shfl_xor_sync(FULLM, se, 2);
        g_attw[q] = e / se;

        float rx = rp[m*3], ry = rp[m*3+1], rz = rp[m*3+2];
        const float* of = g_off + m*96 + h*12 + p*3;
        float sx = rx + of[0], sy = ry + of[1], sz = rz + of[2];
        g_sl[q] = make_float4(sx, sy, sz, sx*sx + sy*sy + sz*sz);
        int key = morton(sx, sy, sz);
        skey[qi] = key;
        atomicAdd(&cnt[key], 1);
    }
    __syncthreads();

    int sv = 0, v = 0;
    if (tid < 512) {
        sv = cnt[tid]; v = sv;
        #pragma unroll
        for (int off = 1; off < 32; off <<= 1) {
            int u = __shfl_up_sync(FULLM, v, off);
            if (lane >= off) v += u;
        }
        if (lane == 31) wsum[w] = v;
    }
    __syncthreads();
    if (tid == 0) {
        int acc = 0;
        #pragma unroll
        for (int i = 0; i < 16; i++) { int t = wsum[i]; wsum[i] = acc; acc += t; }
    }
    __syncthreads();
    if (tid < 512) bstart[tid] = v - sv + wsum[w];
    __syncthreads();
    #pragma unroll
    for (int j = 0; j < 4; j++) {
        int qi = tid + j*1024;
        int slot = atomicAdd(&bstart[skey[qi]], 1);
        g_qperm[b*QPB + slot] = qi;
    }
}

// ============================================================================
// Kernel 3: MEGA — blocks 0..511: knn half-sweeps ; 512..639: val GEMM
// ============================================================================
#define INS(dd, ii) { \
    bool c3 = (dd) < d3, c2 = (dd) < d2, c1 = (dd) < d1, c0 = (dd) < d0; \
    d3 = c3 ? (c2 ? d2 : (dd)) : d3;  i3 = c3 ? (c2 ? i2 : (ii)) : i3; \
    d2 = c2 ? (c1 ? d1 : (dd)) : d2;  i2 = c2 ? (c1 ? i1 : (ii)) : i2; \
    d1 = c1 ? (c0 ? d0 : (dd)) : d1;  i1 = c1 ? (c0 ? i0 : (ii)) : i1; \
    d0 = c0 ? (dd) : d0;              i0 = c0 ? (ii) : i0; }

#define INSV(vv) { \
    bool c3 = (vv) < e3, c2 = (vv) < e2, c1 = (vv) < e1, c0 = (vv) < e0; \
    e3 = c3 ? (c2 ? e2 : (vv)) : e3; \
    e2 = c2 ? (c1 ? e1 : (vv)) : e2; \
    e1 = c1 ? (c0 ? e0 : (vv)) : e1; \
    e0 = c0 ? (vv) : e0; }

#define DIST2(jj, lo, hi) { \
    ulonglong2 a  = sA[jj]; \
    ulonglong2 bb = sB[jj]; \
    u64 dot = mul2(a.x, sx2); \
    dot = fma2(a.y, sy2, dot); \
    dot = fma2(bb.x, sz2, dot); \
    u64 dd2 = fma2(dot, m2, add2(bb.y, sw2)); \
    upk(dd2, lo, hi); }

// half-sweep knn: block sweeps refs [half*512, half*512+512) for 256 queries
__device__ void knn_body(char* sm, int blk) {
    ulonglong2* sA   = (ulonglong2*)(sm);
    ulonglong2* sB   = (ulonglong2*)(sm + 8192);
    int*        sCT  = (int*)(sm + 16384);
    const int b     = blk >> 5;                    // batch-head 0..15
    const int chunk = (blk >> 1) & 15;             // query chunk 0..15
    const int half  = blk & 1;                     // ref half 0/1
    const int n = b & (NB - 1);                    // ref set = rp[b % N]
    const int tid = threadIdx.x;

    for (int j = tid; j < LB/2; j += 256) {
        float4 r0 = g_refPts[n][2*j];
        float4 r1 = g_refPts[n][2*j + 1];
        sA[j] = make_ulonglong2(pk(r0.x, r1.x), pk(r0.y, r1.y));
        sB[j] = make_ulonglong2(pk(r0.z, r1.z), pk(r0.w, r1.w));
    }
    sCT[tid] = g_cellTile[n][tid];
    sCT[tid + 256] = g_cellTile[n][tid + 256];
    __syncthreads();

    const int pos = chunk*256 + tid;               // Morton-sorted position
    const int qi = g_qperm[b*QPB + pos];
    const int q = b*QPB + qi;
    float4 s = g_sl[q];

    const u64 sx2 = pk(s.x, s.x), sy2 = pk(s.y, s.y), sz2 = pk(s.z, s.z), sw2 = pk(s.w, s.w);
    const u64 m2 = pk(-2.f, -2.f);

    // home tile via cell map; seed upper bound dinit (full ref set in smem)
    const int bt = sCT[morton(s.x, s.y, s.z)];
    float e0 = 3.4e38f, e1 = 3.4e38f, e2 = 3.4e38f, e3 = 3.4e38f;
    {
        const int jb = bt*(TS/2);
        #pragma unroll
        for (int j = 0; j < TS/2; j++) {
            float lo, hi;
            DIST2(jb + j, lo, hi);
            INSV(lo);
            INSV(hi);
        }
    }
    const float dinit = e3 * 1.0001f + 1e-7f;      // strict upper bound on final d3

    float d0 = dinit, d1 = dinit, d2 = dinit, d3 = dinit;
    int   i0 = 0, i1 = 0, i2 = 0, i3 = 0;

    // half sweep: 256 pair-iterations; ballot-gated ladder (R8-exact per half)
    const int jb0 = half * (LB/4);
    #pragma unroll 4
    for (int j0 = 0; j0 < LB/4; j0++) {
        const int j = jb0 + j0;
        float lo, hi;
        DIST2(j, lo, hi);
        if (__ballot_sync(FULLM, fminf(lo, hi) < d3)) {
            INS(lo, 2*j);
            INS(hi, 2*j + 1);
        }
    }

    g_pd[q*2 + half] = make_float4(d0, d1, d2, d3);
    g_pi[q*2 + half] = make_int4(i0, i1, i2, i3);
}

// 64x64 val gemm body (unchanged; hidden under knn)
#define AS64(buf,k,m) AsP[(buf)*1024 + (k)*64 + (m)]
#define BS64(buf,k,n) BsP[(buf)*1088 + (k)*68 + (n)]

__device__ void val_gemm_body(char* sm, const float* __restrict__ A,
                              const float* __restrict__ B, const float* __restrict__ bias,
                              int blk) {
    float* AsP = (float*)sm;
    float* BsP = (float*)(sm + 8192);
    const int tid = threadIdx.x;
    const int tx = tid & 15, ty = tid >> 4;
    const int colBase = (blk & 3) * 64;
    const int rowBase = (blk >> 2) * 64;
    float acc[4][4];
    #pragma unroll
    for (int i = 0; i < 4; i++)
        #pragma unroll
        for (int j = 0; j < 4; j++) acc[i][j] = 0.f;

    #pragma unroll
    for (int i = 0; i < 4; i++) {
        int idx = tid + i*256;
        int m = idx >> 4, k = idx & 15;
        AS64(0, k, m) = A[(rowBase + m)*256 + k];
        int k2 = idx >> 6, nn = idx & 63;
        BS64(0, k2, nn) = B[k2*256 + colBase + nn];
    }
    __syncthreads();

    #pragma unroll 4
    for (int k0 = 0; k0 < 256; k0 += 16) {
        const int cur = (k0 >> 4) & 1, nxt = cur ^ 1;
        float ra[4], rb[4];
        const bool more = (k0 + 16) < 256;
        if (more) {
            #pragma unroll
            for (int i = 0; i < 4; i++) {
                int idx = tid + i*256;
                int m = idx >> 4, k = idx & 15;
                ra[i] = A[(rowBase + m)*256 + k0 + 16 + k];
                int k2 = idx >> 6, nn = idx & 63;
                rb[i] = B[(k0 + 16 + k2)*256 + colBase + nn];
            }
        }
        #pragma unroll
        for (int kk = 0; kk < 16; kk++) {
            float4 av = *(const float4*)&AS64(cur, kk, ty*4);
            float4 bv = *(const float4*)&BS64(cur, kk, tx*4);
            float a[4] = {av.x, av.y, av.z, av.w};
            float b[4] = {bv.x, bv.y, bv.z, bv.w};
            #pragma unroll
            for (int i = 0; i < 4; i++)
                #pragma unroll
                for (int j = 0; j < 4; j++)
                    acc[i][j] = fmaf(a[i], b[j], acc[i][j]);
        }
        if (more) {
            #pragma unroll
            for (int i = 0; i < 4; i++) {
                int idx = tid + i*256;
                int m = idx >> 4, k = idx & 15;
                AS64(nxt, k, m) = ra[i];
                int k2 = idx >> 6, nn = idx & 63;
                BS64(nxt, k2, nn) = rb[i];
            }
            __syncthreads();
        }
    }

    #pragma unroll
    for (int i = 0; i < 4; i++) {
        int gm = rowBase + ty*4 + i;
        #pragma unroll
        for (int j = 0; j < 4; j++) {
            int gn = colBase + tx*4 + j;
            g_val[gm*256 + gn] = acc[i][j] + bias[gn];
        }
    }
}

__global__ void mega_k(const float* __restrict__ A,
                       const float* __restrict__ Wv, const float* __restrict__ bv) {
    __shared__ __align__(16) char sm[22528];
    if (blockIdx.x < 512) knn_body(sm, blockIdx.x);
    else                  val_gemm_body(sm, A, Wv, bv, blockIdx.x - 512);
}

// ============================================================================
// Kernel 4: merge the two half-lists + epilogue (256 blocks)
// ============================================================================
#define MRG_STEP(mk, mik) { \
    bool ta = A0 <= B0; \
    mk = ta ? A0 : B0;  mik = ta ? Ai0 : Bi0; \
    A0 = ta ? A1 : A0;  Ai0 = ta ? Ai1 : Ai0; \
    A1 = ta ? A2 : A1;  Ai1 = ta ? Ai2 : Ai1; \
    A2 = ta ? A3 : A2;  Ai2 = ta ? Ai3 : Ai2; \
    A3 = ta ? 3.4e38f : A3; \
    B0 = ta ? B0 : B1;  Bi0 = ta ? Bi0 : Bi1; \
    B1 = ta ? B1 : B2;  Bi1 = ta ? Bi1 : Bi2; \
    B2 = ta ? B2 : B3;  Bi2 = ta ? Bi2 : Bi3; \
    B3 = ta ? B3 : 3.4e38f; }

__global__ void merge_k() {
    const int q = blockIdx.x*256 + threadIdx.x;
    float4 Ad = g_pd[q*2],     Bd = g_pd[q*2 + 1];
    int4   Av = g_pi[q*2],     Bv = g_pi[q*2 + 1];
    float A0 = Ad.x, A1 = Ad.y, A2 = Ad.z, A3 = Ad.w;
    int  Ai0 = Av.x, Ai1 = Av.y, Ai2 = Av.z, Ai3 = Av.w;
    float B0 = Bd.x, B1 = Bd.y, B2 = Bd.z, B3 = Bd.w;
    int  Bi0 = Bv.x, Bi1 = Bv.y, Bi2 = Bv.z, Bi3 = Bv.w;

    float m0, m1, m2v, m3; int mi0, mi1, mi2, mi3;
    MRG_STEP(m0, mi0);
    MRG_STEP(m1, mi1);
    MRG_STEP(m2v, mi2);
    MRG_STEP(m3, mi3);

    const int b = q >> 12;
    const int n = b & (NB - 1);
    float t0 = sqrtf(fmaxf(m0, 1e-12f));
    float t1 = sqrtf(fmaxf(m1, 1e-12f));
    float t2 = sqrtf(fmaxf(m2v, 1e-12f));
    float t3 = sqrtf(fmaxf(m3, 1e-12f));
    float w0 = 1.f/(t0 + 1e-8f), w1 = 1.f/(t1 + 1e-8f);
    float w2 = 1.f/(t2 + 1e-8f), w3 = 1.f/(t3 + 1e-8f);
    float scale = g_attw[q] / (w0 + w1 + w2 + w3);

    *(int4*)  (g_idx + 4*q) = make_int4(g_refIdx[n][mi0], g_refIdx[n][mi1],
                                        g_refIdx[n][mi2], g_refIdx[n][mi3]);
    *(float4*)(g_w   + 4*q) = make_float4(w0*scale, w1*scale, w2*scale, w3*scale);
}

// ============================================================================
// Kernel 5: gather values + weighted sum (2 channels/thread, 1024 blocks)
// ============================================================================
__global__ void combine_k() {
    int t = blockIdx.x*256 + threadIdx.x;
    int g = t >> 4;
    int c2 = (t & 15) << 1;
    int b = g >> 10, l = g & (LB - 1);
    int n_q = b >> 3, h_q = b & 7;
    int n_v = b & 1,  h_v = b >> 1;
    const float* vb = g_val + n_v*(LB*EB) + h_v*DB + c2;
    int qb = (b*QPB + l*PB)*KK;
    const int4*   ip = (const int4*)  (g_idx + qb);
    const float4* wp = (const float4*)(g_w   + qb);
    float2 acc = make_float2(0.f, 0.f);
    #pragma unroll
    for (int j = 0; j < 4; j++) {
        int4   ii = ip[j];
        float4 ww = wp[j];
        float2 v;
        v = *(const float2*)(vb + ii.x*EB);
        acc.x = fmaf(ww.x, v.x, acc.x); acc.y = fmaf(ww.x, v.y, acc.y);
        v = *(const float2*)(vb + ii.y*EB);
        acc.x = fmaf(ww.y, v.x, acc.x); acc.y = fmaf(ww.y, v.y, acc.y);
        v = *(const float2*)(vb + ii.z*EB);
        acc.x = fmaf(ww.z, v.x, acc.x); acc.y = fmaf(ww.z, v.y, acc.y);
        v = *(const float2*)(vb + ii.w*EB);
        acc.x = fmaf(ww.w, v.x, acc.x); acc.y = fmaf(ww.w, v.y, acc.y);
    }
    *(float2*)(g_A + (n_q*LB + l)*EB + h_q*DB + c2) = acc;
}

// ============================================================================
// Kernel 6: output GEMM — 32-row x 64-col tiles, grid (4,64)
// ============================================================================
__global__ void out_gemm_k(const float* __restrict__ B,
                           const float* __restrict__ bias,
                           float* __restrict__ C) {
    __shared__ __align__(16) char sm[12800];
    float* AsP = (float*)sm;
    float* BsP = (float*)(sm + 4096);
    const float* A = g_A;
    const int tid = threadIdx.x;
    const int tx = tid & 15, ty = tid >> 4;
    const int rowBase = blockIdx.y * 32;
    const int colBase = blockIdx.x * 64;
    float acc[2][4];
    #pragma unroll
    for (int i = 0; i < 2; i++)
        #pragma unroll
        for (int j = 0; j < 4; j++) acc[i][j] = 0.f;

    #pragma unroll
    for (int i = 0; i < 2; i++) {
        int idx = tid + i*256;
        int m = idx >> 4, k = idx & 15;
        AS32(0, k, m) = A[(rowBase + m)*256 + k];
    }
    #pragma unroll
    for (int i = 0; i < 4; i++) {
        int idx = tid + i*256;
        int k2 = idx >> 6, nn = idx & 63;
        BS32(0, k2, nn) = B[k2*256 + colBase + nn];
    }
    __syncthreads();

    #pragma unroll 4
    for (int k0 = 0; k0 < 256; k0 += 16) {
        const int cur = (k0 >> 4) & 1, nxt = cur ^ 1;
        float ra[2], rb[4];
        const bool more = (k0 + 16) < 256;
        if (more) {
            #pragma unroll
            for (int i = 0; i < 2; i++) {
                int idx = tid + i*256;
                int m = idx >> 4, k = idx & 15;
                ra[i] = A[(rowBase + m)*256 + k0 + 16 + k];
            }
            #pragma unroll
            for (int i = 0; i < 4; i++) {
                int idx = tid + i*256;
                int k2 = idx >> 6, nn = idx & 63;
                rb[i] = B[(k0 + 16 + k2)*256 + colBase + nn];
            }
        }
        #pragma unroll
        for (int kk = 0; kk < 16; kk++) {
            float2 av = *(const float2*)&AS32(cur, kk, ty*2);
            float4 bv = *(const float4*)&BS32(cur, kk, tx*4);
            float a[2] = {av.x, av.y};
            float b[4] = {bv.x, bv.y, bv.z, bv.w};
            #pragma unroll
            for (int i = 0; i < 2; i++)
                #pragma unroll
                for (int j = 0; j < 4; j++)
                    acc[i][j] = fmaf(a[i], b[j], acc[i][j]);
        }
        if (more) {
            #pragma unroll
            for (int i = 0; i < 2; i++) {
                int idx = tid + i*256;
                int m = idx >> 4, k = idx & 15;
                AS32(nxt, k, m) = ra[i];
            }
            #pragma unroll
            for (int i = 0; i < 4; i++) {
                int idx = tid + i*256;
                int k2 = idx >> 6, nn = idx & 63;
                BS32(nxt, k2, nn) = rb[i];
            }
            __syncthreads();
        }
    }

    #pragma unroll
    for (int i = 0; i < 2; i++) {
        int gm = rowBase + ty*2 + i;
        #pragma unroll
        for (int j = 0; j < 4; j++) {
            int gn = colBase + tx*4 + j;
            C[gm*256 + gn] = acc[i][j] + bias[gn];
        }
    }
}

// ---------------------------------------------------------------------------
extern "C" void kernel_launch(void* const* d_in, const int* in_sizes, int n_in,
                              void* d_out, int out_size) {
    const float* q      = (const float*)d_in[0];
    const float* rp     = (const float*)d_in[1];
    const float* W_off  = (const float*)d_in[2];
    const float* b_off  = (const float*)d_in[3];
    const float* W_attn = (const float*)d_in[4];
    const float* b_attn = (const float*)d_in[5];
    const float* W_val  = (const float*)d_in[6];
    const float* b_val  = (const float*)d_in[7];
    const float* W_out  = (const float*)d_in[8];
    const float* b_out  = (const float*)d_in[9];
    float* out = (float*)d_out;

    dim3 blk(256);
    oa_refsort_k<<<130, blk>>>(q, W_off, b_off, W_attn, b_attn, rp);
    sortprep_k  <<<16, 1024>>>(rp);
    mega_k      <<<640, blk>>>(q, W_val, b_val);
    merge_k     <<<256, blk>>>();
    combine_k   <<<1024, blk>>>();
    out_gemm_k  <<<dim3(4, 64), blk>>>(W_out, b_out, out);
}

// round 16
// speedup vs baseline: 1.1420x; 1.1420x over previous
#include <cuda_runtime.h>

// Problem constants
#define NB 2
#define LB 1024
#define EB 256
#define HB 8
#define PB 4
#define KK 4
#define DB 32
#define MROWS (NB*LB)        // 2048
#define NH (NB*HB)           // 16
#define QPB (LB*PB)          // 4096 queries per batch-head
#define QTOT (NH*QPB)        // 65536
#define TS 16                // refs per tile
#define FULLM 0xffffffffu

// ---------------- scratch (device globals) ---------------------------------
__device__ float  g_val [MROWS*EB];
__device__ float  g_off [MROWS*96];
__device__ float  g_attn[MROWS*32];
__device__ float  g_attw[QTOT];
__device__ float4 g_sl  [QTOT];             // sampling loc (x,y,z,|s|^2)
__device__ int    g_qperm[QTOT];            // per-b permutation (Morton sorted)
__device__ float4 g_refPts[NB][LB];         // Morton-sorted refs (x,y,z,|r|^2)
__device__ int    g_refIdx[NB][LB];         // original ref index
__device__ int    g_cellTile[NB][512];      // Morton cell -> covering tile
__device__ int    g_idx [QTOT*KK];
__device__ float  g_w   [QTOT*KK];
__device__ float  g_A   [MROWS*EB];

// ---------------- packed f32x2 helpers (Blackwell) --------------------------
typedef unsigned long long u64;
__device__ __forceinline__ u64 pk(float lo, float hi) {
    u64 v; asm("mov.b64 %0, {%1, %2};" : "=l"(v) : "f"(lo), "f"(hi)); return v;
}
__device__ __forceinline__ void upk(u64 v, float& lo, float& hi) {
    asm("mov.b64 {%0, %1}, %2;" : "=f"(lo), "=f"(hi) : "l"(v));
}
__device__ __forceinline__ u64 fma2(u64 a, u64 b, u64 c) {
    u64 d; asm("fma.rn.f32x2 %0, %1, %2, %3;" : "=l"(d) : "l"(a), "l"(b), "l"(c)); return d;
}
__device__ __forceinline__ u64 mul2(u64 a, u64 b) {
    u64 d; asm("mul.rn.f32x2 %0, %1, %2;" : "=l"(d) : "l"(a), "l"(b)); return d;
}
__device__ __forceinline__ u64 add2(u64 a, u64 b) {
    u64 d; asm("add.rn.f32x2 %0, %1, %2;" : "=l"(d) : "l"(a), "l"(b)); return d;
}

// ---------------- Morton helpers -------------------------------------------
__device__ __forceinline__ int spread3(int x) {
    return (x & 1) | ((x & 2) << 2) | ((x & 4) << 4);
}
__device__ __forceinline__ int cell8(float v) {
    int c = (int)floorf(v * 8.f);
    return min(max(c, 0), 7);
}
__device__ __forceinline__ int morton(float x, float y, float z) {
    return spread3(cell8(x)) | (spread3(cell8(y)) << 1) | (spread3(cell8(z)) << 2);
}

// ============================================================================
// Kernel 1: fused off/attn GEMM 32-row tiles (blocks 0..127) + refsort (128,129)
// ============================================================================

__device__ void refsort_body(char* sm, const float* __restrict__ rp, int n) {
    float* sx        = (float*)(sm);
    float* sy        = (float*)(sm + 4096);
    float* sz        = (float*)(sm + 8192);
    int*   sidx      = (int*)  (sm + 12288);
    int*   skey      = (int*)  (sm + 16384);
    int*   sortedKey = (int*)  (sm + 20480);
    int*   cnt       = (int*)  (sm + 24576);
    int*   bstart    = (int*)  (sm + 26624);
    int*   sCT       = (int*)  (sm + 28672);
    int*   wsum      = (int*)  (sm + 30720);
    const int tid = threadIdx.x;
    const int lane = tid & 31, w = tid >> 5;
    const float* rpb = rp + n*LB*3;

    cnt[tid] = 0; cnt[tid + 256] = 0;
    __syncthreads();
    #pragma unroll
    for (int j = 0; j < 4; j++) {
        int i = tid + j*256;
        float x = rpb[3*i], y = rpb[3*i+1], z = rpb[3*i+2];
        int key = morton(x, y, z);
        skey[i] = key;
        atomicAdd(&cnt[key], 1);
    }
    __syncthreads();
    int c0 = cnt[2*tid], c1 = cnt[2*tid + 1];
    int s = c0 + c1, v = s;
    #pragma unroll
    for (int off = 1; off < 32; off <<= 1) {
        int u = __shfl_up_sync(FULLM, v, off);
        if (lane >= off) v += u;
    }
    if (lane == 31) wsum[w] = v;
    __syncthreads();
    if (tid == 0) {
        int acc = 0;
        #pragma unroll
        for (int i = 0; i < 8; i++) { int t = wsum[i]; wsum[i] = acc; acc += t; }
    }
    __syncthreads();
    int excl = v - s + wsum[w];
    bstart[2*tid] = excl; bstart[2*tid + 1] = excl + c0;
    __syncthreads();
    #pragma unroll
    for (int j = 0; j < 4; j++) {
        int i = tid + j*256;
        int slot = atomicAdd(&bstart[skey[i]], 1);
        sx[slot] = rpb[3*i]; sy[slot] = rpb[3*i+1]; sz[slot] = rpb[3*i+2];
        sidx[slot] = i;
        sortedKey[slot] = skey[i];
    }
    __syncthreads();
    #pragma unroll
    for (int j = 0; j < 4; j++) {
        int i = tid + j*256;
        float x = sx[i], y = sy[i], z = sz[i];
        g_refPts[n][i] = make_float4(x, y, z, x*x + y*y + z*z);
        g_refIdx[n][i] = sidx[i];
    }

    sCT[tid] = -1; sCT[tid + 256] = -1;
    __syncthreads();
    #pragma unroll
    for (int j = 0; j < 4; j++) {
        int slot = tid + j*256;
        int k = sortedKey[slot];
        if (slot == 0 || sortedKey[slot-1] != k) sCT[k] = slot >> 4;
    }
    __syncthreads();
    for (int off = 1; off < 512; off <<= 1) {
        int a0 = sCT[tid],       a1 = sCT[tid + 256];
        int b0 = (tid >= off)       ? sCT[tid - off]       : -1;
        int b1 = (tid + 256 >= off) ? sCT[tid + 256 - off] : -1;
        __syncthreads();
        sCT[tid]       = (a0 != -1) ? a0 : b0;
        sCT[tid + 256] = (a1 != -1) ? a1 : b1;
        __syncthreads();
    }
    g_cellTile[n][tid]       = (sCT[tid] == -1) ? 0 : sCT[tid];
    g_cellTile[n][tid + 256] = (sCT[tid + 256] == -1) ? 0 : sCT[tid + 256];
}

// ---- 32-row x 64-col double-buffered gemm helpers --------------------------
#define AS32(buf,k,m) AsP[(buf)*512  + (k)*32 + (m)]
#define BS32(buf,k,n) BsP[(buf)*1088 + (k)*68 + (n)]

__device__ void oa_gemm_body(char* sm, const float* __restrict__ A,
                             const float* __restrict__ Wo, const float* __restrict__ bo,
                             const float* __restrict__ Wa, const float* __restrict__ ba,
                             int blk) {
    float* AsP = (float*)sm;
    float* BsP = (float*)(sm + 4096);
    const int tid = threadIdx.x;
    const int tx = tid & 15, ty = tid >> 4;
    const int colBase = (blk & 1) * 64;
    const int rowBase = (blk >> 1) * 32;
    float acc[2][4];
    #pragma unroll
    for (int i = 0; i < 2; i++)
        #pragma unroll
        for (int j = 0; j < 4; j++) acc[i][j] = 0.f;

    #pragma unroll
    for (int i = 0; i < 2; i++) {
        int idx = tid + i*256;
        int m = idx >> 4, k = idx & 15;
        AS32(0, k, m) = A[(rowBase + m)*256 + k];
    }
    #pragma unroll
    for (int i = 0; i < 4; i++) {
        int idx = tid + i*256;
        int k2 = idx >> 6, nn = idx & 63;
        int gn = colBase + nn;
        BS32(0, k2, nn) = (gn < 96) ? Wo[k2*96 + gn] : Wa[k2*32 + (gn - 96)];
    }
    __syncthreads();

    #pragma unroll 4
    for (int k0 = 0; k0 < 256; k0 += 16) {
        const int cur = (k0 >> 4) & 1, nxt = cur ^ 1;
        float ra[2], rb[4];
        const bool more = (k0 + 16) < 256;
        if (more) {
            #pragma unroll
            for (int i = 0; i < 2; i++) {
                int idx = tid + i*256;
                int m = idx >> 4, k = idx & 15;
                ra[i] = A[(rowBase + m)*256 + k0 + 16 + k];
            }
            #pragma unroll
            for (int i = 0; i < 4; i++) {
                int idx = tid + i*256;
                int k2 = idx >> 6, nn = idx & 63;
                int gn = colBase + nn;
                int gk = k0 + 16 + k2;
                rb[i] = (gn < 96) ? Wo[gk*96 + gn] : Wa[gk*32 + (gn - 96)];
            }
        }
        #pragma unroll
        for (int kk = 0; kk < 16; kk++) {
            float2 av = *(const float2*)&AS32(cur, kk, ty*2);
            float4 bv = *(const float4*)&BS32(cur, kk, tx*4);
            float a[2] = {av.x, av.y};
            float b[4] = {bv.x, bv.y, bv.z, bv.w};
            #pragma unroll
            for (int i = 0; i < 2; i++)
                #pragma unroll
                for (int j = 0; j < 4; j++)
                    acc[i][j] = fmaf(a[i], b[j], acc[i][j]);
        }
        if (more) {
            #pragma unroll
            for (int i = 0; i < 2; i++) {
                int idx = tid + i*256;
                int m = idx >> 4, k = idx & 15;
                AS32(nxt, k, m) = ra[i];
            }
            #pragma unroll
            for (int i = 0; i < 4; i++) {
                int idx = tid + i*256;
                int k2 = idx >> 6, nn = idx & 63;
                BS32(nxt, k2, nn) = rb[i];
            }
            __syncthreads();
        }
    }

    #pragma unroll
    for (int i = 0; i < 2; i++) {
        int gm = rowBase + ty*2 + i;
        #pragma unroll
        for (int j = 0; j < 4; j++) {
            int gn = colBase + tx*4 + j;
            float v = acc[i][j];
            if (gn < 96) g_off[gm*96 + gn]         = v + bo[gn];
            else         g_attn[gm*32 + (gn - 96)] = v + ba[gn - 96];
        }
    }
}

__global__ void oa_refsort_k(const float* __restrict__ A,
                             const float* __restrict__ Wo, const float* __restrict__ bo,
                             const float* __restrict__ Wa, const float* __restrict__ ba,
                             const float* __restrict__ rp) {
    __shared__ __align__(16) char sm[30752];
    if (blockIdx.x < 128) oa_gemm_body(sm, A, Wo, bo, Wa, ba, blockIdx.x);
    else                  refsort_body(sm, rp, blockIdx.x - 128);
}

// ============================================================================
// Kernel 2: fused prep + Morton counting sort (16 blocks, 1024 thr)
// ============================================================================
__global__ void sortprep_k(const float* __restrict__ rp) {
    __shared__ int skey[QPB];
    __shared__ int cnt[512];
    __shared__ int bstart[512];
    __shared__ int wsum[16];
    const int b = blockIdx.x, tid = threadIdx.x;
    const int lane = tid & 31, w = tid >> 5;
    const int n = b >> 3, h = b & 7;

    if (tid < 512) cnt[tid] = 0;
    __syncthreads();

    #pragma unroll
    for (int j = 0; j < 4; j++) {
        int qi = tid + j*1024;
        int l = qi >> 2, p = qi & 3;
        int m = n*LB + l;
        int q = b*QPB + qi;

        float x = g_attn[m*32 + h*4 + p];
        float mx = x;
        mx = fmaxf(mx, __shfl_xor_sync(FULLM, mx, 1));
        mx = fmaxf(mx, __shfl_xor_sync(FULLM, mx, 2));
        float e = expf(x - mx);
        float se = e;
        se += __shfl_xor_sync(FULLM, se, 1);
        se += __shfl_xor_sync(FULLM, se, 2);
        g_attw[q] = e / se;

        float rx = rp[m*3], ry = rp[m*3+1], rz = rp[m*3+2];
        const float* of = g_off + m*96 + h*12 + p*3;
        float sx = rx + of[0], sy = ry + of[1], sz = rz + of[2];
        g_sl[q] = make_float4(sx, sy, sz, sx*sx + sy*sy + sz*sz);
        int key = morton(sx, sy, sz);
        skey[qi] = key;
        atomicAdd(&cnt[key], 1);
    }
    __syncthreads();

    int sv = 0, v = 0;
    if (tid < 512) {
        sv = cnt[tid]; v = sv;
        #pragma unroll
        for (int off = 1; off < 32; off <<= 1) {
            int u = __shfl_up_sync(FULLM, v, off);
            if (lane >= off) v += u;
        }
        if (lane == 31) wsum[w] = v;
    }
    __syncthreads();
    if (tid == 0) {
        int acc = 0;
        #pragma unroll
        for (int i = 0; i < 16; i++) { int t = wsum[i]; wsum[i] = acc; acc += t; }
    }
    __syncthreads();
    if (tid < 512) bstart[tid] = v - sv + wsum[w];
    __syncthreads();
    #pragma unroll
    for (int j = 0; j < 4; j++) {
        int qi = tid + j*1024;
        int slot = atomicAdd(&bstart[skey[qi]], 1);
        g_qperm[b*QPB + slot] = qi;
    }
}

// ============================================================================
// Kernel 3: MEGA — blocks 0..255: knn ; blocks 256..383: val GEMM (64x64)
// ============================================================================
#define INS(dd, ii) { \
    bool c3 = (dd) < d3, c2 = (dd) < d2, c1 = (dd) < d1, c0 = (dd) < d0; \
    d3 = c3 ? (c2 ? d2 : (dd)) : d3;  i3 = c3 ? (c2 ? i2 : (ii)) : i3; \
    d2 = c2 ? (c1 ? d1 : (dd)) : d2;  i2 = c2 ? (c1 ? i1 : (ii)) : i2; \
    d1 = c1 ? (c0 ? d0 : (dd)) : d1;  i1 = c1 ? (c0 ? i0 : (ii)) : i1; \
    d0 = c0 ? (dd) : d0;              i0 = c0 ? (ii) : i0; }

#define INSV(vv) { \
    bool c3 = (vv) < e3, c2 = (vv) < e2, c1 = (vv) < e1, c0 = (vv) < e0; \
    e3 = c3 ? (c2 ? e2 : (vv)) : e3; \
    e2 = c2 ? (c1 ? e1 : (vv)) : e2; \
    e1 = c1 ? (c0 ? e0 : (vv)) : e1; \
    e0 = c0 ? (vv) : e0; }

#define DIST2(jj, lo, hi) { \
    ulonglong2 a  = sA[jj]; \
    ulonglong2 bb = sB[jj]; \
    u64 dot = mul2(a.x, sx2); \
    dot = fma2(a.y, sy2, dot); \
    dot = fma2(bb.x, sz2, dot); \
    u64 dd2 = fma2(dot, m2, add2(bb.y, sw2)); \
    upk(dd2, lo, hi); }

__device__ void knn_body(char* sm, int blk) {
    ulonglong2* sA   = (ulonglong2*)(sm);
    ulonglong2* sB   = (ulonglong2*)(sm + 8192);
    int*        sIdx = (int*)(sm + 16384);
    int*        sCT  = (int*)(sm + 20480);
    const int b = blk >> 4;
    const int chunk = blk & 15;
    const int n = b & (NB - 1);                    // ref set = rp[b % N]
    const int tid = threadIdx.x;

    for (int j = tid; j < LB/2; j += 256) {
        float4 r0 = g_refPts[n][2*j];
        float4 r1 = g_refPts[n][2*j + 1];
        sA[j] = make_ulonglong2(pk(r0.x, r1.x), pk(r0.y, r1.y));
        sB[j] = make_ulonglong2(pk(r0.z, r1.z), pk(r0.w, r1.w));
        sIdx[2*j]     = g_refIdx[n][2*j];
        sIdx[2*j + 1] = g_refIdx[n][2*j + 1];
    }
    sCT[tid] = g_cellTile[n][tid];
    sCT[tid + 256] = g_cellTile[n][tid + 256];
    __syncthreads();

    const int pos = chunk*256 + tid;
    const int qi = g_qperm[b*QPB + pos];
    const int q = b*QPB + qi;
    float4 s = g_sl[q];

    const u64 sx2 = pk(s.x, s.x), sy2 = pk(s.y, s.y), sz2 = pk(s.z, s.z), sw2 = pk(s.w, s.w);
    const u64 m2 = pk(-2.f, -2.f);

    const int bt = sCT[morton(s.x, s.y, s.z)];
    float e0 = 3.4e38f, e1 = 3.4e38f, e2 = 3.4e38f, e3 = 3.4e38f;
    {
        const int jb = bt*(TS/2);
        #pragma unroll
        for (int j = 0; j < TS/2; j++) {
            float lo, hi;
            DIST2(jb + j, lo, hi);
            INSV(lo);
            INSV(hi);
        }
    }
    const float dinit = e3 * 1.0001f + 1e-7f;

    float d0 = dinit, d1 = dinit, d2 = dinit, d3 = dinit;
    int   i0 = 0, i1 = 0, i2 = 0, i3 = 0;

    // sweep: 2 pairs (4 refs) per ballot — independent DIST2 chains for ILP
    #pragma unroll 4
    for (int j = 0; j < LB/2; j += 2) {
        float lo0, hi0, lo1, hi1;
        DIST2(j,     lo0, hi0);
        DIST2(j + 1, lo1, hi1);
        float m4 = fminf(fminf(lo0, hi0), fminf(lo1, hi1));
        if (__ballot_sync(FULLM, m4 < d3)) {
            INS(lo0, 2*j);
            INS(hi0, 2*j + 1);
            INS(lo1, 2*j + 2);
            INS(hi1, 2*j + 3);
        }
    }

    float t0 = sqrtf(fmaxf(d0, 1e-12f));
    float t1 = sqrtf(fmaxf(d1, 1e-12f));
    float t2 = sqrtf(fmaxf(d2, 1e-12f));
    float t3 = sqrtf(fmaxf(d3, 1e-12f));
    float w0 = 1.f/(t0 + 1e-8f), w1 = 1.f/(t1 + 1e-8f);
    float w2 = 1.f/(t2 + 1e-8f), w3 = 1.f/(t3 + 1e-8f);
    float scale = g_attw[q] / (w0 + w1 + w2 + w3);

    *(int4*)  (g_idx + 4*q) = make_int4(sIdx[i0], sIdx[i1], sIdx[i2], sIdx[i3]);
    *(float4*)(g_w   + 4*q) = make_float4(w0*scale, w1*scale, w2*scale, w3*scale);
}

// 64x64 val gemm body (unchanged; hidden under knn)
#define AS64(buf,k,m) AsP[(buf)*1024 + (k)*64 + (m)]
#define BS64(buf,k,n) BsP[(buf)*1088 + (k)*68 + (n)]

__device__ void val_gemm_body(char* sm, const float* __restrict__ A,
                              const float* __restrict__ B, const float* __restrict__ bias,
                              int blk) {
    float* AsP = (float*)sm;
    float* BsP = (float*)(sm + 8192);
    const int tid = threadIdx.x;
    const int tx = tid & 15, ty = tid >> 4;
    const int colBase = (blk & 3) * 64;
    const int rowBase = (blk >> 2) * 64;
    float acc[4][4];
    #pragma unroll
    for (int i = 0; i < 4; i++)
        #pragma unroll
        for (int j = 0; j < 4; j++) acc[i][j] = 0.f;

    #pragma unroll
    for (int i = 0; i < 4; i++) {
        int idx = tid + i*256;
        int m = idx >> 4, k = idx & 15;
        AS64(0, k, m) = A[(rowBase + m)*256 + k];
        int k2 = idx >> 6, nn = idx & 63;
        BS64(0, k2, nn) = B[k2*256 + colBase + nn];
    }
    __syncthreads();

    #pragma unroll 4
    for (int k0 = 0; k0 < 256; k0 += 16) {
        const int cur = (k0 >> 4) & 1, nxt = cur ^ 1;
        float ra[4], rb[4];
        const bool more = (k0 + 16) < 256;
        if (more) {
            #pragma unroll
            for (int i = 0; i < 4; i++) {
                int idx = tid + i*256;
                int m = idx >> 4, k = idx & 15;
                ra[i] = A[(rowBase + m)*256 + k0 + 16 + k];
                int k2 = idx >> 6, nn = idx & 63;
                rb[i] = B[(k0 + 16 + k2)*256 + colBase + nn];
            }
        }
        #pragma unroll
        for (int kk = 0; kk < 16; kk++) {
            float4 av = *(const float4*)&AS64(cur, kk, ty*4);
            float4 bv = *(const float4*)&BS64(cur, kk, tx*4);
            float a[4] = {av.x, av.y, av.z, av.w};
            float b[4] = {bv.x, bv.y, bv.z, bv.w};
            #pragma unroll
            for (int i = 0; i < 4; i++)
                #pragma unroll
                for (int j = 0; j < 4; j++)
                    acc[i][j] = fmaf(a[i], b[j], acc[i][j]);
        }
        if (more) {
            #pragma unroll
            for (int i = 0; i < 4; i++) {
                int idx = tid + i*256;
                int m = idx >> 4, k = idx & 15;
                AS64(nxt, k, m) = ra[i];
                int k2 = idx >> 6, nn = idx & 63;
                BS64(nxt, k2, nn) = rb[i];
            }
            __syncthreads();
        }
    }

    #pragma unroll
    for (int i = 0; i < 4; i++) {
        int gm = rowBase + ty*4 + i;
        #pragma unroll
        for (int j = 0; j < 4; j++) {
            int gn = colBase + tx*4 + j;
            g_val[gm*256 + gn] = acc[i][j] + bias[gn];
        }
    }
}

__global__ void mega_k(const float* __restrict__ A,
                       const float* __restrict__ Wv, const float* __restrict__ bv) {
    __shared__ __align__(16) char sm[22528];
    if (blockIdx.x < 256) knn_body(sm, blockIdx.x);
    else                  val_gemm_body(sm, A, Wv, bv, blockIdx.x - 256);
}

// ============================================================================
// Kernel 4: gather values + weighted sum (2 channels/thread, 1024 blocks)
// ============================================================================
__global__ void combine_k() {
    int t = blockIdx.x*256 + threadIdx.x;
    int g = t >> 4;
    int c2 = (t & 15) << 1;
    int b = g >> 10, l = g & (LB - 1);
    int n_q = b >> 3, h_q = b & 7;
    int n_v = b & 1,  h_v = b >> 1;
    const float* vb = g_val + n_v*(LB*EB) + h_v*DB + c2;
    int qb = (b*QPB + l*PB)*KK;
    const int4*   ip = (const int4*)  (g_idx + qb);
    const float4* wp = (const float4*)(g_w   + qb);
    float2 acc = make_float2(0.f, 0.f);
    #pragma unroll
    for (int j = 0; j < 4; j++) {
        int4   ii = ip[j];
        float4 ww = wp[j];
        float2 v;
        v = *(const float2*)(vb + ii.x*EB);
        acc.x = fmaf(ww.x, v.x, acc.x); acc.y = fmaf(ww.x, v.y, acc.y);
        v = *(const float2*)(vb + ii.y*EB);
        acc.x = fmaf(ww.y, v.x, acc.x); acc.y = fmaf(ww.y, v.y, acc.y);
        v = *(const float2*)(vb + ii.z*EB);
        acc.x = fmaf(ww.z, v.x, acc.x); acc.y = fmaf(ww.z, v.y, acc.y);
        v = *(const float2*)(vb + ii.w*EB);
        acc.x = fmaf(ww.w, v.x, acc.x); acc.y = fmaf(ww.w, v.y, acc.y);
    }
    *(float2*)(g_A + (n_q*LB + l)*EB + h_q*DB + c2) = acc;
}

// ============================================================================
// Kernel 5: output GEMM — 32-row x 64-col tiles, grid (4,64), double-buffered
// ============================================================================
__global__ void out_gemm_k(const float* __restrict__ B,
                           const float* __restrict__ bias,
                           float* __restrict__ C) {
    __shared__ __align__(16) char sm[12800];
    float* AsP = (float*)sm;
    float* BsP = (float*)(sm + 4096);
    const float* A = g_A;
    const int tid = threadIdx.x;
    const int tx = tid & 15, ty = tid >> 4;
    const int rowBase = blockIdx.y * 32;
    const int colBase = blockIdx.x * 64;
    float acc[2][4];
    #pragma unroll
    for (int i = 0; i < 2; i++)
        #pragma unroll
        for (int j = 0; j < 4; j++) acc[i][j] = 0.f;

    #pragma unroll
    for (int i = 0; i < 2; i++) {
        int idx = tid + i*256;
        int m = idx >> 4, k = idx & 15;
        AS32(0, k, m) = A[(rowBase + m)*256 + k];
    }
    #pragma unroll
    for (int i = 0; i < 4; i++) {
        int idx = tid + i*256;
        int k2 = idx >> 6, nn = idx & 63;
        BS32(0, k2, nn) = B[k2*256 + colBase + nn];
    }
    __syncthreads();

    #pragma unroll 4
    for (int k0 = 0; k0 < 256; k0 += 16) {
        const int cur = (k0 >> 4) & 1, nxt = cur ^ 1;
        float ra[2], rb[4];
        const bool more = (k0 + 16) < 256;
        if (more) {
            #pragma unroll
            for (int i = 0; i < 2; i++) {
                int idx = tid + i*256;
                int m = idx >> 4, k = idx & 15;
                ra[i] = A[(rowBase + m)*256 + k0 + 16 + k];
            }
            #pragma unroll
            for (int i = 0; i < 4; i++) {
                int idx = tid + i*256;
                int k2 = idx >> 6, nn = idx & 63;
                rb[i] = B[(k0 + 16 + k2)*256 + colBase + nn];
            }
        }
        #pragma unroll
        for (int kk = 0; kk < 16; kk++) {
            float2 av = *(const float2*)&AS32(cur, kk, ty*2);
            float4 bv = *(const float4*)&BS32(cur, kk, tx*4);
            float a[2] = {av.x, av.y};
            float b[4] = {bv.x, bv.y, bv.z, bv.w};
            #pragma unroll
            for (int i = 0; i < 2; i++)
                #pragma unroll
                for (int j = 0; j < 4; j++)
                    acc[i][j] = fmaf(a[i], b[j], acc[i][j]);
        }
        if (more) {
            #pragma unroll
            for (int i = 0; i < 2; i++) {
                int idx = tid + i*256;
                int m = idx >> 4, k = idx & 15;
                AS32(nxt, k, m) = ra[i];
            }
            #pragma unroll
            for (int i = 0; i < 4; i++) {
                int idx = tid + i*256;
                int k2 = idx >> 6, nn = idx & 63;
                BS32(nxt, k2, nn) = rb[i];
            }
            __syncthreads();
        }
    }

    #pragma unroll
    for (int i = 0; i < 2; i++) {
        int gm = rowBase + ty*2 + i;
        #pragma unroll
        for (int j = 0; j < 4; j++) {
            int gn = colBase + tx*4 + j;
            C[gm*256 + gn] = acc[i][j] + bias[gn];
        }
    }
}

// ---------------------------------------------------------------------------
extern "C" void kernel_launch(void* const* d_in, const int* in_sizes, int n_in,
                              void* d_out, int out_size) {
    const float* q      = (const float*)d_in[0];
    const float* rp     = (const float*)d_in[1];
    const float* W_off  = (const float*)d_in[2];
    const float* b_off  = (const float*)d_in[3];
    const float* W_attn = (const float*)d_in[4];
    const float* b_attn = (const float*)d_in[5];
    const float* W_val  = (const float*)d_in[6];
    const float* b_val  = (const float*)d_in[7];
    const float* W_out  = (const float*)d_in[8];
    const float* b_out  = (const float*)d_in[9];
    float* out = (float*)d_out;

    dim3 blk(256);
    oa_refsort_k<<<130, blk>>>(q, W_off, b_off, W_attn, b_attn, rp);
    sortprep_k  <<<16, 1024>>>(rp);
    mega_k      <<<384, blk>>>(q, W_val, b_val);
    combine_k   <<<1024, blk>>>();
    out_gemm_k  <<<dim3(4, 64), blk>>>(W_out, b_out, out);
}